// round 6
// baseline (speedup 1.0000x reference)
#include <cuda_runtime.h>
#include <math.h>

// Problem constants (fixed by the reference setup)
#define Bd   128
#define Vd   4
#define Dd   128
#define Nd   512           // B*V
#define ANCH 4             // anchors per block
#define GRID (Nd / ANCH)   // 128 blocks
#define NT   512           // threads per block
#define NW   16            // warps per block
#define WROWS (Nd / NW)    // 32 rows owned per warp
#define PHR  16            // rows per phase (2 phases)
#define RS   132           // padded row stride (conflict-free LDS.128)
#define WSEG ((ANCH + PHR) * RS)   // per-warp smem floats: 4 anchors + 16 rows

#define DYN_FLOATS (NW * WSEG + ANCH * Nd)
#define DYN_BYTES  (DYN_FLOATS * 4)

// Scratch (device globals — no allocation allowed)
__device__ float        g_part[GRID];
__device__ unsigned int g_cntp[GRID];
__device__ unsigned int g_done = 0;

__global__ void __launch_bounds__(NT, 1)
fused_triplet_kernel(const float* __restrict__ feat,
                     const int*   __restrict__ labels,
                     float*       __restrict__ out) {
    extern __shared__ float smem[];
    float* wseg = smem + (threadIdx.x >> 5) * WSEG;  // this warp's private segment
    float* sdm  = smem + NW * WSEG;                  // ANCH * Nd distance rows

    __shared__ int          slab[Nd];
    __shared__ int          spos[ANCH][Nd];
    __shared__ float        spp[ANCH][Nd];
    __shared__ int          snpos[ANCH];
    __shared__ float        swsum[NW];
    __shared__ unsigned int swcnt[NW];
    __shared__ int          sIsLast;

    const int t    = threadIdx.x;
    const int w    = t >> 5;
    const int lane = t & 31;
    const int blk  = blockIdx.x;

    // row n of emb <- features[n & 127, n >> 7, :]
    auto row_ptr = [&](int n) -> const float* {
        return feat + (size_t)(n & (Bd - 1)) * (Vd * Dd) + (n >> 7) * Dd;
    };

    slab[t] = labels[t & (Bd - 1)];
    if (t < ANCH) snpos[t] = 0;

    // ---- anchors: LDG into regs (for norms) + STS into private segment ----
    float4 av0 = reinterpret_cast<const float4*>(row_ptr(blk * ANCH + 0))[lane];
    float4 av1 = reinterpret_cast<const float4*>(row_ptr(blk * ANCH + 1))[lane];
    float4 av2 = reinterpret_cast<const float4*>(row_ptr(blk * ANCH + 2))[lane];
    float4 av3 = reinterpret_cast<const float4*>(row_ptr(blk * ANCH + 3))[lane];
    reinterpret_cast<float4*>(wseg + 0 * RS)[lane] = av0;
    reinterpret_cast<float4*>(wseg + 1 * RS)[lane] = av1;
    reinterpret_cast<float4*>(wseg + 2 * RS)[lane] = av2;
    reinterpret_cast<float4*>(wseg + 3 * RS)[lane] = av3;

    // per-warp anchor inverse norms (from the regs we already hold)
    float n0 = av0.x*av0.x + av0.y*av0.y + av0.z*av0.z + av0.w*av0.w;
    float n1 = av1.x*av1.x + av1.y*av1.y + av1.z*av1.z + av1.w*av1.w;
    float n2 = av2.x*av2.x + av2.y*av2.y + av2.z*av2.z + av2.w*av2.w;
    float n3 = av3.x*av3.x + av3.y*av3.y + av3.z*av3.z + av3.w*av3.w;
#pragma unroll
    for (int o = 16; o > 0; o >>= 1) {
        n0 += __shfl_xor_sync(0xffffffffu, n0, o);
        n1 += __shfl_xor_sync(0xffffffffu, n1, o);
        n2 += __shfl_xor_sync(0xffffffffu, n2, o);
        n3 += __shfl_xor_sync(0xffffffffu, n3, o);
    }
    const float ina0 = 1.0f / sqrtf(n0);
    const float ina1 = 1.0f / sqrtf(n1);
    const float ina2 = 1.0f / sqrtf(n2);
    const float ina3 = 1.0f / sqrtf(n3);

    const int r  = lane & 15;   // row within phase
    const int kh = lane >> 4;   // k-half: 0 or 1

    const float4* a0p = reinterpret_cast<const float4*>(wseg + 0 * RS + kh * 64);
    const float4* a1p = reinterpret_cast<const float4*>(wseg + 1 * RS + kh * 64);
    const float4* a2p = reinterpret_cast<const float4*>(wseg + 2 * RS + kh * 64);
    const float4* a3p = reinterpret_cast<const float4*>(wseg + 3 * RS + kh * 64);

#pragma unroll
    for (int p = 0; p < 2; p++) {
        const int rbase = w * WROWS + p * PHR;

        // ---- stage 16 rows, two batches of 8 (MLP=8, bounded regs) ----
        float4 rg[8];
#pragma unroll
        for (int rr = 0; rr < 8; rr++)
            rg[rr] = reinterpret_cast<const float4*>(row_ptr(rbase + rr))[lane];
#pragma unroll
        for (int rr = 0; rr < 8; rr++)
            reinterpret_cast<float4*>(wseg + (ANCH + rr) * RS)[lane] = rg[rr];
#pragma unroll
        for (int rr = 0; rr < 8; rr++)
            rg[rr] = reinterpret_cast<const float4*>(row_ptr(rbase + 8 + rr))[lane];
#pragma unroll
        for (int rr = 0; rr < 8; rr++)
            reinterpret_cast<float4*>(wseg + (ANCH + 8 + rr) * RS)[lane] = rg[rr];
        __syncwarp();

        // ---- compute: lane owns (row r, k-half kh) ----
        const float4* rowp =
            reinterpret_cast<const float4*>(wseg + (ANCH + r) * RS + kh * 64);
        float d0 = 0.f, d1 = 0.f, d2 = 0.f, d3 = 0.f, sq = 0.f;
#pragma unroll
        for (int c = 0; c < 16; c++) {
            float4 f  = rowp[c];
            float4 a0 = a0p[c];
            float4 a1 = a1p[c];
            float4 a2 = a2p[c];
            float4 a3 = a3p[c];
            sq += f.x * f.x  + f.y * f.y  + f.z * f.z  + f.w * f.w;
            d0 += f.x * a0.x + f.y * a0.y + f.z * a0.z + f.w * a0.w;
            d1 += f.x * a1.x + f.y * a1.y + f.z * a1.z + f.w * a1.w;
            d2 += f.x * a2.x + f.y * a2.y + f.z * a2.z + f.w * a2.w;
            d3 += f.x * a3.x + f.y * a3.y + f.z * a3.z + f.w * a3.w;
        }
        // combine the two k-halves (partner lane = lane ^ 16)
        d0 += __shfl_xor_sync(0xffffffffu, d0, 16);
        d1 += __shfl_xor_sync(0xffffffffu, d1, 16);
        d2 += __shfl_xor_sync(0xffffffffu, d2, 16);
        d3 += __shfl_xor_sync(0xffffffffu, d3, 16);
        sq += __shfl_xor_sync(0xffffffffu, sq, 16);

        if (kh == 0) {
            float invnj = 1.0f / sqrtf(sq);
            int gj = rbase + r;
            float c0 = d0 * ina0 * invnj;
            float c1 = d1 * ina1 * invnj;
            float c2 = d2 * ina2 * invnj;
            float c3 = d3 * ina3 * invnj;
            sdm[0 * Nd + gj] = sqrtf(fmaxf(2.f - 2.f * c0, 0.f));
            sdm[1 * Nd + gj] = sqrtf(fmaxf(2.f - 2.f * c1, 0.f));
            sdm[2 * Nd + gj] = sqrtf(fmaxf(2.f - 2.f * c2, 0.f));
            sdm[3 * Nd + gj] = sqrtf(fmaxf(2.f - 2.f * c3, 0.f));
        }
        __syncwarp();   // row buffer reused next phase
    }

    __syncthreads();   // sdm complete (the ONLY block barrier before triplets)

    // ---- gather positive lists for all 4 anchors in one pass ----
    {
        int myl = slab[t];
#pragma unroll
        for (int i = 0; i < ANCH; i++) {
            int a = blk * ANCH + i;
            if (myl == slab[a] && t != a) {
                int k = atomicAdd(&snpos[i], 1);
                spos[i][k] = t;
            }
        }
    }
    __syncthreads();
    {
#pragma unroll
        for (int i = 0; i < ANCH; i++) {
            if (t < snpos[i]) spp[i][t] = sdm[i * Nd + spos[i][t]];
        }
    }
    __syncthreads();

    // ---- triplet reduction: thread t = candidate negative n ----
    float        lsum = 0.0f;
    unsigned int lcnt = 0;
    {
        int myl = slab[t];
#pragma unroll
        for (int i = 0; i < ANCH; i++) {
            int a = blk * ANCH + i;
            if (myl != slab[a]) {
                float dan = sdm[i * Nd + t];
                int P = snpos[i];
#pragma unroll 4
                for (int q = 0; q < P; q++) {
                    float diff = spp[i][q] - dan;   // margin = 0
                    if (diff > 0.0f) { lsum += diff; lcnt++; }
                }
            }
        }
    }

    // ---- block reduce (sum, count) ----
#pragma unroll
    for (int o = 16; o > 0; o >>= 1) {
        lsum += __shfl_xor_sync(0xffffffffu, lsum, o);
        lcnt += __shfl_xor_sync(0xffffffffu, lcnt, o);
    }
    if (lane == 0) { swsum[w] = lsum; swcnt[w] = lcnt; }
    __syncthreads();

    if (t == 0) {
        float bs = 0.0f; unsigned int bc = 0;
#pragma unroll
        for (int k = 0; k < NW; k++) { bs += swsum[k]; bc += swcnt[k]; }
        g_part[blk] = bs;
        g_cntp[blk] = bc;
        __threadfence();
        unsigned int old = atomicAdd(&g_done, 1);
        sIsLast = (old == GRID - 1);
    }
    __syncthreads();

    // ---- last block finalizes (AvgNonZeroReducer) ----
    if (sIsLast) {
        __threadfence();
        float        s = 0.0f;
        unsigned int c = 0;
        if (t < GRID) {
            s = ((volatile float*)g_part)[t];
            c = ((volatile unsigned int*)g_cntp)[t];
        }
#pragma unroll
        for (int o = 16; o > 0; o >>= 1) {
            s += __shfl_xor_sync(0xffffffffu, s, o);
            c += __shfl_xor_sync(0xffffffffu, c, o);
        }
        if (t < GRID && lane == 0) { swsum[w] = s; swcnt[w] = c; }
        __syncthreads();
        if (t == 0) {
            float S = swsum[0] + swsum[1] + swsum[2] + swsum[3];
            unsigned int C = swcnt[0] + swcnt[1] + swcnt[2] + swcnt[3];
            out[0] = (C > 0) ? (S / (float)C) : 0.0f;
            g_done = 0;   // reset for next graph replay
        }
    }
}

extern "C" void kernel_launch(void* const* d_in, const int* in_sizes, int n_in,
                              void* d_out, int out_size) {
    const float* feat   = (const float*)d_in[0];   // [128, 4, 128] float32
    const int*   labels = (const int*)d_in[1];     // [128] int32
    float*       out    = (float*)d_out;           // scalar float32

    cudaFuncSetAttribute(fused_triplet_kernel,
                         cudaFuncAttributeMaxDynamicSharedMemorySize,
                         DYN_BYTES);
    fused_triplet_kernel<<<GRID, NT, DYN_BYTES>>>(feat, labels, out);
}